// round 15
// baseline (speedup 1.0000x reference)
#include <cuda_runtime.h>
#include <cuda_bf16.h>
#include <cstdint>

#define NB   32
#define NOPE 2048
#define NMAC 1024
#define DIN  64
#define DOUT 128

#define CHUNK  32
#define NCH    (NOPE / CHUNK)    // 64

#define PACK_BLOCKS ((NB * (NOPE / 32) * NMAC) / 256)   // 8192
#define K1_BLOCKS   (NB * (NOPE / 32))                  // 2048
#define K2_BLOCKS   (NB * (NMAC / 32))                  // 1024
#define PRE_BLOCKS  (PACK_BLOCKS + K1_BLOCKS + K2_BLOCKS)  // 11264 = 1024*11

// ---------------- scratch (device globals; no allocations) ----------------
__device__ __nv_bfloat16 g_h[(size_t)NB * NOPE * DOUT];   // h_ope bf16 [b][o][k]
__device__ float  g_ao [NB * NOPE];
__device__ float2 g_eo12[NB * NOPE];                      // {exp(ao), exp(0.2 ao)}
__device__ float g_am [NB * NMAC];
__device__ float g_em1[NB * NMAC];
__device__ float g_em2[NB * NMAC];
__device__ uint32_t g_adjp[(size_t)NB * (NOPE / 32) * NMAC];  // packed adjacency bits

// ---------------- K_pre: interleaved pack + h_ope + h_res ----------------
// groups of 11 blocks: 8 pack, 2 h_ope, 1 h_res  -> all pipes busy simultaneously
__global__ void __launch_bounds__(256) k_pre(
    const int* __restrict__ adj, const int* __restrict__ bidx,
    const float* __restrict__ fop, const float* __restrict__ owm,
    const float* __restrict__ oal,
    const float* __restrict__ fma, const float* __restrict__ rwm,
    const float* __restrict__ mwm, const float* __restrict__ mal,
    float* __restrict__ out)
{
    __shared__ float wT_s[DIN * 129];
    __shared__ float f_s[32 * 65];
    __shared__ float v_s[DIN];

    const int t   = threadIdx.x;
    const int bid = blockIdx.x;
    const int grp = bid / 11;
    const int r   = bid - grp * 11;

    // ---------- branch A: adjacency bit-pack ----------
    if (r < 8) {
        const int idx = (grp * 8 + r) * 256 + t;    // [b][ow][m]
        const int m  = idx & (NMAC - 1);
        const int ow = (idx >> 10) & 63;
        const int b  = idx >> 16;
        const int aidx = bidx[b];
        const int* p = adj + ((size_t)aidx * NOPE + ow * 32) * NMAC + m;
        uint32_t w = 0;
#pragma unroll
        for (int i = 0; i < 32; ++i)
            w |= ((uint32_t)p[(size_t)i * NMAC] & 1u) << i;
        g_adjp[idx] = w;
        return;
    }

    const bool isOpe = r < 10;
    const int  blk   = isOpe ? (grp * 2 + (r - 8)) : grp;
    const float* feat = isOpe ? fop : fma;
    const float* wmat = isOpe ? owm : rwm;   // GEMM weights (ope_w / res_w)
    const float* avw  = isOpe ? owm : mwm;   // attention-vector weights
    const float* aal  = isOpe ? oal : mal;   // attention alphas
    const int nrowT = isOpe ? NOPE : NMAC;
    const int b  = isOpe ? (blk >> 6) : (blk >> 5);
    const int r0 = isOpe ? ((blk & 63) * 32) : ((blk & 31) * 32);

    for (int i = t; i < DOUT * DIN; i += 256) {
        int k = i >> 6, d = i & 63;
        wT_s[d * 129 + k] = wmat[i];
    }
    const float* fsrc = feat + (size_t)(b * nrowT + r0) * DIN;
    for (int i = t; i < 32 * DIN; i += 256) {
        int rr = i >> 6, d = i & 63;
        f_s[rr * 65 + d] = fsrc[i];
    }
    if (t < DIN) {
        float s = 0.f;
        for (int k = 0; k < DOUT; ++k) s += avw[k * DIN + t] * aal[k];
        v_s[t] = s;
    }
    __syncthreads();

    const int kg = t & 31;
    const int rg = t >> 5;
    float acc[4][4];
#pragma unroll
    for (int rr = 0; rr < 4; ++rr)
#pragma unroll
        for (int j = 0; j < 4; ++j) acc[rr][j] = 0.f;

    for (int d = 0; d < DIN; ++d) {
        float wv[4];
#pragma unroll
        for (int j = 0; j < 4; ++j) wv[j] = wT_s[d * 129 + kg + 32 * j];
#pragma unroll
        for (int rr = 0; rr < 4; ++rr) {
            float f = f_s[(rg * 4 + rr) * 65 + d];
#pragma unroll
            for (int j = 0; j < 4; ++j) acc[rr][j] += f * wv[j];
        }
    }

    if (isOpe) {
        __nv_bfloat16* hdst = g_h + (size_t)(b * NOPE + r0) * DOUT;
#pragma unroll
        for (int rr = 0; rr < 4; ++rr)
#pragma unroll
            for (int j = 0; j < 4; ++j)
                hdst[(rg * 4 + rr) * DOUT + kg + 32 * j] = __float2bfloat16(acc[rr][j]);
        if (t < 32) {
            float ao = 0.f;
            for (int d = 0; d < DIN; ++d) ao += f_s[t * 65 + d] * v_s[d];
            int idx = b * NOPE + r0 + t;
            g_ao[idx]   = ao;
            g_eo12[idx] = make_float2(expf(ao), expf(0.2f * ao));
        }
    } else {
        float* odst = out + (size_t)(b * NMAC + r0) * DOUT;
#pragma unroll
        for (int rr = 0; rr < 4; ++rr)
#pragma unroll
            for (int j = 0; j < 4; ++j)
                odst[(rg * 4 + rr) * DOUT + kg + 32 * j] = acc[rr][j];
        if (t < 32) {
            float am = 0.f;
            for (int d = 0; d < DIN; ++d) am += f_s[t * 65 + d] * v_s[d];
            int idx = b * NMAC + r0 + t;
            g_am[idx]  = am;
            g_em1[idx] = expf(am);
            g_em2[idx] = expf(0.2f * am);
        }
    }
}

// ---------------- K3: fused masked-softmax aggregation + normalize ----------------
__device__ __forceinline__ void ldsm4t(uint32_t& r0, uint32_t& r1, uint32_t& r2,
                                       uint32_t& r3, uint32_t addr)
{
    asm volatile("ldmatrix.sync.aligned.m8n8.x4.trans.shared.b16 {%0,%1,%2,%3}, [%4];\n"
                 : "=r"(r0), "=r"(r1), "=r"(r2), "=r"(r3) : "r"(addr));
}
__device__ __forceinline__ void mma16816(float* c, const uint32_t* a,
                                         uint32_t b0, uint32_t b1)
{
    asm volatile("mma.sync.aligned.m16n8k16.row.col.f32.bf16.bf16.f32 "
                 "{%0,%1,%2,%3}, {%4,%5,%6,%7}, {%8,%9}, {%0,%1,%2,%3};\n"
                 : "+f"(c[0]), "+f"(c[1]), "+f"(c[2]), "+f"(c[3])
                 : "r"(a[0]), "r"(a[1]), "r"(a[2]), "r"(a[3]), "r"(b0), "r"(b1));
}
__device__ __forceinline__ void cpa16(uint32_t s, const void* g)
{
    asm volatile("cp.async.cg.shared.global [%0], [%1], 16;\n" :: "r"(s), "l"(g));
}
__device__ __forceinline__ void cpa_commit()
{
    asm volatile("cp.async.commit_group;\n" ::);
}

// dynamic smem layout (bytes): 3-stage H pipeline, 2-stage W pipeline
#define H_PITCH   136
#define H_BYTES   (CHUNK * H_PITCH * 2)     // 8704
#define OFF_H     0
#define OFF_W     (3 * H_BYTES)                   // 26112
#define OFF_AO    (OFF_W + 2 * H_BYTES)           // 43520
#define OFF_EO12  (OFF_AO + NOPE * 4)             // 51712
#define OFF_ZS    (OFF_EO12 + NOPE * 8)           // 68096
#define SMEM_K3   (OFF_ZS + 512)                  // 68608

// grid 256 = 32 b x 8 m-tiles; 256 threads; 2 CTAs/SM -> single wave.
__global__ void __launch_bounds__(256, 2) k3_attn(float* __restrict__ out)
{
    extern __shared__ __align__(16) char sm[];
    __nv_bfloat16* Ws    = (__nv_bfloat16*)(sm + OFF_W);
    float*         aoS   = (float*)(sm + OFF_AO);
    float2*        eo12S = (float2*)(sm + OFF_EO12);
    float*         zs    = (float*)(sm + OFF_ZS);

    const int t  = threadIdx.x;
    const int bx = blockIdx.x;
    const int b  = bx >> 3;
    const int mt = bx & 7;
    const int m0 = mt * 128;

    const uint32_t smbase = (uint32_t)__cvta_generic_to_shared(sm);
    const char* hgbase = (const char*)(g_h + (size_t)b * NOPE * DOUT);

    const int m  = t & 127;
    const int oh = t >> 7;

    // packed adjacency: one word per chunk per thread (layout [b][ow][m])
    const uint32_t* adjw = g_adjp + (size_t)b * (NOPE / 32) * NMAC + m0 + m;

    auto stageH = [&](int ch, int buf) {
        const char* hg = hgbase + (size_t)ch * CHUNK * DOUT * 2;
        uint32_t hD = smbase + OFF_H + (uint32_t)(buf * H_BYTES);
#pragma unroll
        for (int j = 0; j < 2; ++j) {
            int i = t + 256 * j, rr = i >> 4, s = i & 15;
            cpa16(hD + (uint32_t)(rr * H_PITCH * 2 + s * 16),
                  hg + (size_t)rr * DOUT * 2 + s * 16);
        }
    };

    // prologue: H chunks 0,1 in flight
    stageH(0, 0); cpa_commit();
    stageH(1, 1); cpa_commit();
    uint32_t w0 = __ldg(adjw);

    // per-o scalar tables (full o-range; overlaps prologue loads)
    {
        const float*  a0 = g_ao   + b * NOPE;
        const float2* e  = g_eo12 + b * NOPE;
        for (int i = t; i < NOPE; i += 256) {
            aoS[i]   = a0[i];
            eo12S[i] = e[i];
        }
    }

    const float amv = g_am [b * NMAC + m0 + m];
    const float em1 = g_em1[b * NMAC + m0 + m];
    const float em2 = g_em2[b * NMAC + m0 + m];
    const float negam = -amv;

    const int warp = t >> 5, lane = t & 31;
    const int kw   = warp * 16;
    const int g    = lane >> 2, tig = lane & 3;

    const int a_or = (lane & 7) + ((lane & 16) >> 1);
    const uint32_t aAdr0 = smbase + OFF_H + (uint32_t)((a_or * H_PITCH + kw + (lane & 8)) * 2);
    const uint32_t bAdr0 = smbase + OFF_W + (uint32_t)(lane * H_PITCH * 2);

    float acc[64];
#pragma unroll
    for (int i = 0; i < 64; ++i) acc[i] = 0.f;
    float zacc = 0.f;

    // W-gen for chunk ch into W buffer wb
    auto wgen = [&](int ch, int wb, uint32_t bits) {
        const int ob = ch * CHUNK;
        __nv_bfloat16* W = Ws + wb * (CHUNK * H_PITCH);
#pragma unroll
        for (int j = 0; j < 16; ++j) {
            int ol = oh + 2 * j;
            float w = 0.f;
            if ((bits >> ol) & 1u) {
                float  ao = aoS[ob + ol];
                float2 e  = eo12S[ob + ol];
                w = (ao >= negam) ? e.x * em1 : e.y * em2;
            }
            W[ol * H_PITCH + m] = __float2bfloat16(w);
            zacc += w;
        }
    };

    __syncthreads();            // scalar tables visible
    wgen(0, 0, w0);             // W chunk 0
    uint32_t wnxt = __ldg(adjw + NMAC);   // adjacency word for chunk 1

    for (int ch = 0; ch < NCH; ++ch) {
        asm volatile("cp.async.wait_group 1;\n" ::);   // H chunk ch landed
        __syncthreads();   // W-gen(ch) visible; mma(ch-1) done; H(ch) visible

        if (ch + 2 < NCH) stageH(ch + 2, (ch + 2) % 3);
        cpa_commit();
        uint32_t wnn = (ch + 2 < NCH) ? __ldg(adjw + (size_t)(ch + 2) * NMAC) : 0;

        // interleave: generate next W while issuing this chunk's mma
        if (ch + 1 < NCH) wgen(ch + 1, (ch + 1) & 1, wnxt);

        const uint32_t aAdr = aAdr0 + (uint32_t)((ch % 3) * H_BYTES);
        const uint32_t bAdr = bAdr0 + (uint32_t)((ch & 1) * H_BYTES);
        uint32_t A0[4], A1[4];
        ldsm4t(A0[0], A0[1], A0[2], A0[3], aAdr);
        ldsm4t(A1[0], A1[1], A1[2], A1[3], aAdr + 16 * H_PITCH * 2);
#pragma unroll
        for (int nt = 0; nt < 16; ++nt) {
            uint32_t B0, B1, B2, B3;
            ldsm4t(B0, B1, B2, B3, bAdr + (uint32_t)(nt * 16));
            mma16816(acc + nt * 4, A0, B0, B1);
            mma16816(acc + nt * 4, A1, B2, B3);
        }
        wnxt = wnn;
    }

    // ---- full Z reduction (complete in this CTA) ----
    __syncthreads();
    if (t < 128) zs[t] = zacc;
    __syncthreads();
    if (t >= 128) zs[t - 128] += zacc;
    __syncthreads();

    // ---- epilogue: out += numer / Z (out already holds exact h_res) ----
    float* ob = out + ((size_t)b * NMAC + m0) * DOUT;
#pragma unroll
    for (int nt = 0; nt < 16; ++nt) {
        int ma = nt * 8 + tig * 2;
        float iz0 = 1.0f / zs[ma];
        float iz1 = 1.0f / zs[ma + 1];
        int k = kw + g;
        float* p0 = ob + (size_t)ma * DOUT + k;
        float* p1 = ob + (size_t)(ma + 1) * DOUT + k;
        p0[0] += acc[nt * 4 + 0] * iz0;
        p1[0] += acc[nt * 4 + 1] * iz1;
        p0[8] += acc[nt * 4 + 2] * iz0;
        p1[8] += acc[nt * 4 + 3] * iz1;
    }
}

// ---------------- launch ----------------
extern "C" void kernel_launch(void* const* d_in, const int* in_sizes, int n_in,
                              void* d_out, int out_size)
{
    const int*   adj  = (const int*)d_in[0];
    const int*   bidx = (const int*)d_in[1];
    const float* fop  = (const float*)d_in[2];
    const float* fma  = (const float*)d_in[3];
    const float* ow   = (const float*)d_in[4];
    const float* mw   = (const float*)d_in[5];
    const float* oa   = (const float*)d_in[6];
    const float* ma   = (const float*)d_in[7];
    const float* rw   = (const float*)d_in[8];
    float* out = (float*)d_out;

    static bool attr_set = false;
    if (!attr_set) {
        cudaFuncSetAttribute(k3_attn, cudaFuncAttributeMaxDynamicSharedMemorySize, SMEM_K3);
        attr_set = true;
    }

    k_pre<<<PRE_BLOCKS, 256>>>(adj, bidx, fop, ow, oa, fma, rw, mw, ma, out);
    k3_attn<<<NB * 8, 256, SMEM_K3>>>(out);
}

// round 16
// speedup vs baseline: 1.1213x; 1.1213x over previous
#include <cuda_runtime.h>
#include <cuda_bf16.h>
#include <cstdint>

#define NB   32
#define NOPE 2048
#define NMAC 1024
#define DIN  64
#define DOUT 128

#define CHUNK  32
#define NCH    (NOPE / CHUNK)    // 64

#define PACK_BLOCKS (NB * (NOPE / 32))                  // 2048 (int4 pack)
#define K1_BLOCKS   (NB * (NOPE / 32))                  // 2048
#define K2_BLOCKS   (NB * (NMAC / 32))                  // 1024
#define PRE_BLOCKS  (PACK_BLOCKS + K1_BLOCKS + K2_BLOCKS)  // 5120 = 1024*5

// ---------------- scratch (device globals; no allocations) ----------------
__device__ __nv_bfloat16 g_h[(size_t)NB * NOPE * DOUT];   // h_ope bf16 [b][o][k]
__device__ float4 g_sc[NB * NOPE];                        // {ao, exp(ao), exp(.2ao), 0}
__device__ float g_am [NB * NMAC];
__device__ float g_em1[NB * NMAC];
__device__ float g_em2[NB * NMAC];
__device__ uint32_t g_adjp[(size_t)NB * (NOPE / 32) * NMAC];  // packed adjacency bits

// ---------------- K_pre: interleaved pack + h_ope + h_res ----------------
// groups of 5 blocks: 2 pack, 2 h_ope, 1 h_res  -> pipes overlap from t=0
__global__ void __launch_bounds__(256) k_pre(
    const int* __restrict__ adj, const int* __restrict__ bidx,
    const float* __restrict__ fop, const float* __restrict__ owm,
    const float* __restrict__ oal,
    const float* __restrict__ fma, const float* __restrict__ rwm,
    const float* __restrict__ mwm, const float* __restrict__ mal,
    float* __restrict__ out)
{
    __shared__ float wT_s[DIN * 129];
    __shared__ float f_s[32 * 65];
    __shared__ float v_s[DIN];

    const int t   = threadIdx.x;
    const int bid = blockIdx.x;
    const int grp = bid / 5;
    const int r   = bid - grp * 5;

    // ---------- branch A: adjacency bit-pack (int4-vectorized) ----------
    if (r < 2) {
        const int pid = grp * 2 + r;        // [b][ow], 0..2047
        const int b  = pid >> 6;
        const int ow = pid & 63;
        const int aidx = bidx[b];
        // thread t packs m = 4t .. 4t+3
        const int4* p = (const int4*)(adj + ((size_t)aidx * NOPE + ow * 32) * NMAC) + t;
        uint32_t w0 = 0, w1 = 0, w2 = 0, w3 = 0;
#pragma unroll
        for (int i = 0; i < 32; ++i) {
            int4 v = p[(size_t)i * (NMAC / 4)];
            w0 |= ((uint32_t)v.x & 1u) << i;
            w1 |= ((uint32_t)v.y & 1u) << i;
            w2 |= ((uint32_t)v.z & 1u) << i;
            w3 |= ((uint32_t)v.w & 1u) << i;
        }
        uint4 wv = make_uint4(w0, w1, w2, w3);
        ((uint4*)g_adjp)[((size_t)b * 64 + ow) * (NMAC / 4) + t] = wv;
        return;
    }

    const bool isOpe = r < 4;
    const int  blk   = isOpe ? (grp * 2 + (r - 2)) : grp;
    const float* feat = isOpe ? fop : fma;
    const float* wmat = isOpe ? owm : rwm;   // GEMM weights (ope_w / res_w)
    const float* avw  = isOpe ? owm : mwm;   // attention-vector weights
    const float* aal  = isOpe ? oal : mal;   // attention alphas
    const int nrowT = isOpe ? NOPE : NMAC;
    const int b  = isOpe ? (blk >> 6) : (blk >> 5);
    const int r0 = isOpe ? ((blk & 63) * 32) : ((blk & 31) * 32);

    for (int i = t; i < DOUT * DIN; i += 256) {
        int k = i >> 6, d = i & 63;
        wT_s[d * 129 + k] = wmat[i];
    }
    const float* fsrc = feat + (size_t)(b * nrowT + r0) * DIN;
    for (int i = t; i < 32 * DIN; i += 256) {
        int rr = i >> 6, d = i & 63;
        f_s[rr * 65 + d] = fsrc[i];
    }
    if (t < DIN) {
        float s = 0.f;
        for (int k = 0; k < DOUT; ++k) s += avw[k * DIN + t] * aal[k];
        v_s[t] = s;
    }
    __syncthreads();

    const int kg = t & 31;
    const int rg = t >> 5;
    float acc[4][4];
#pragma unroll
    for (int rr = 0; rr < 4; ++rr)
#pragma unroll
        for (int j = 0; j < 4; ++j) acc[rr][j] = 0.f;

    for (int d = 0; d < DIN; ++d) {
        float wv[4];
#pragma unroll
        for (int j = 0; j < 4; ++j) wv[j] = wT_s[d * 129 + kg + 32 * j];
#pragma unroll
        for (int rr = 0; rr < 4; ++rr) {
            float f = f_s[(rg * 4 + rr) * 65 + d];
#pragma unroll
            for (int j = 0; j < 4; ++j) acc[rr][j] += f * wv[j];
        }
    }

    if (isOpe) {
        __nv_bfloat16* hdst = g_h + (size_t)(b * NOPE + r0) * DOUT;
#pragma unroll
        for (int rr = 0; rr < 4; ++rr)
#pragma unroll
            for (int j = 0; j < 4; ++j)
                hdst[(rg * 4 + rr) * DOUT + kg + 32 * j] = __float2bfloat16(acc[rr][j]);
        if (t < 32) {
            float ao = 0.f;
            for (int d = 0; d < DIN; ++d) ao += f_s[t * 65 + d] * v_s[d];
            int idx = b * NOPE + r0 + t;
            g_sc[idx] = make_float4(ao, expf(ao), expf(0.2f * ao), 0.f);
        }
    } else {
        float* odst = out + (size_t)(b * NMAC + r0) * DOUT;
#pragma unroll
        for (int rr = 0; rr < 4; ++rr)
#pragma unroll
            for (int j = 0; j < 4; ++j)
                odst[(rg * 4 + rr) * DOUT + kg + 32 * j] = acc[rr][j];
        if (t < 32) {
            float am = 0.f;
            for (int d = 0; d < DIN; ++d) am += f_s[t * 65 + d] * v_s[d];
            int idx = b * NMAC + r0 + t;
            g_am[idx]  = am;
            g_em1[idx] = expf(am);
            g_em2[idx] = expf(0.2f * am);
        }
    }
}

// ---------------- K3: fused masked-softmax aggregation + normalize ----------------
__device__ __forceinline__ void ldsm4t(uint32_t& r0, uint32_t& r1, uint32_t& r2,
                                       uint32_t& r3, uint32_t addr)
{
    asm volatile("ldmatrix.sync.aligned.m8n8.x4.trans.shared.b16 {%0,%1,%2,%3}, [%4];\n"
                 : "=r"(r0), "=r"(r1), "=r"(r2), "=r"(r3) : "r"(addr));
}
__device__ __forceinline__ void mma16816(float* c, const uint32_t* a,
                                         uint32_t b0, uint32_t b1)
{
    asm volatile("mma.sync.aligned.m16n8k16.row.col.f32.bf16.bf16.f32 "
                 "{%0,%1,%2,%3}, {%4,%5,%6,%7}, {%8,%9}, {%0,%1,%2,%3};\n"
                 : "+f"(c[0]), "+f"(c[1]), "+f"(c[2]), "+f"(c[3])
                 : "r"(a[0]), "r"(a[1]), "r"(a[2]), "r"(a[3]), "r"(b0), "r"(b1));
}
__device__ __forceinline__ void cpa16(uint32_t s, const void* g)
{
    asm volatile("cp.async.cg.shared.global [%0], [%1], 16;\n" :: "r"(s), "l"(g));
}
__device__ __forceinline__ void cpa_commit()
{
    asm volatile("cp.async.commit_group;\n" ::);
}

// dynamic smem layout (bytes); 3-stage H pipeline, single W buffer (R14 structure)
#define H_PITCH   136
#define H_BYTES   (CHUNK * H_PITCH * 2)     // 8704
#define OFF_H     0
#define OFF_W     (3 * H_BYTES)                   // 26112
#define OFF_SC    (OFF_W + H_BYTES)               // 34816
#define OFF_ZS    (OFF_SC + NOPE * 16)            // 67584
#define SMEM_K3   (OFF_ZS + 512)                  // 68096

// grid 256 = 32 b x 8 m-tiles; 256 threads; 2 CTAs/SM -> single wave.
__global__ void __launch_bounds__(256, 2) k3_attn(float* __restrict__ out)
{
    extern __shared__ __align__(16) char sm[];
    __nv_bfloat16* Ws  = (__nv_bfloat16*)(sm + OFF_W);
    float4*        scS = (float4*)(sm + OFF_SC);
    float*         zs  = (float*)(sm + OFF_ZS);

    const int t  = threadIdx.x;
    const int bx = blockIdx.x;
    const int b  = bx >> 3;
    const int mt = bx & 7;
    const int m0 = mt * 128;

    const uint32_t smbase = (uint32_t)__cvta_generic_to_shared(sm);
    const char* hgbase = (const char*)(g_h + (size_t)b * NOPE * DOUT);

    const int m  = t & 127;
    const int oh = t >> 7;

    // packed adjacency: one word per chunk per thread (layout [b][ow][m])
    const uint32_t* adjw = g_adjp + (size_t)b * (NOPE / 32) * NMAC + m0 + m;

    // stage H chunk ch into buffer buf
    auto stageH = [&](int ch, int buf) {
        const char* hg = hgbase + (size_t)ch * CHUNK * DOUT * 2;
        uint32_t hD = smbase + OFF_H + (uint32_t)(buf * H_BYTES);
#pragma unroll
        for (int j = 0; j < 2; ++j) {
            int i = t + 256 * j, rr = i >> 4, s = i & 15;
            cpa16(hD + (uint32_t)(rr * H_PITCH * 2 + s * 16),
                  hg + (size_t)rr * DOUT * 2 + s * 16);
        }
    };

    // prologue: H chunks 0,1 in flight; adj word 0 in register
    stageH(0, 0); cpa_commit();
    stageH(1, 1); cpa_commit();
    uint32_t wcur = __ldg(adjw);

    // fused per-o scalar table (overlaps prologue loads)
    {
        const float4* s0 = g_sc + b * NOPE;
        for (int i = t; i < NOPE; i += 256) scS[i] = s0[i];
    }

    const float amv = g_am [b * NMAC + m0 + m];
    const float em1 = g_em1[b * NMAC + m0 + m];
    const float em2 = g_em2[b * NMAC + m0 + m];
    const float negam = -amv;

    const int warp = t >> 5, lane = t & 31;
    const int kw   = warp * 16;
    const int g    = lane >> 2, tig = lane & 3;

    const int a_or = (lane & 7) + ((lane & 16) >> 1);
    const uint32_t aAdr0 = smbase + OFF_H + (uint32_t)((a_or * H_PITCH + kw + (lane & 8)) * 2);
    const uint32_t aBdr  = smbase + OFF_W + (uint32_t)(lane * H_PITCH * 2);

    float acc[64];
#pragma unroll
    for (int i = 0; i < 64; ++i) acc[i] = 0.f;
    float zacc = 0.f;

    for (int ch = 0; ch < NCH; ++ch) {
        const int buf = ch % 3;
        asm volatile("cp.async.wait_group 1;\n" ::);   // H chunk ch landed
        __syncthreads();                                // visible; old buffer free

        if (ch + 2 < NCH) stageH(ch + 2, (ch + 2) % 3);
        cpa_commit();

        // prefetch next adjacency word (latency covered by W-gen + mma)
        uint32_t wnext = 0;
        if (ch + 1 < NCH) wnext = __ldg(adjw + (size_t)(ch + 1) * NMAC);

        // ---- W-gen from packed bits + fused scalar table ----
        {
            const float4* sc = scS + ch * CHUNK;
            const uint32_t bits = wcur;
#pragma unroll
            for (int j = 0; j < 16; ++j) {
                int ol = oh + 2 * j;
                float w = 0.f;
                if ((bits >> ol) & 1u) {
                    float4 s = sc[ol];
                    w = (s.x >= negam) ? s.y * em1 : s.z * em2;
                }
                Ws[ol * H_PITCH + m] = __float2bfloat16(w);
                zacc += w;
            }
        }
        __syncthreads();

        // ---- mma phase (32 o per chunk) ----
        const uint32_t aAdr = aAdr0 + (uint32_t)(buf * H_BYTES);
        uint32_t A0[4], A1[4];
        ldsm4t(A0[0], A0[1], A0[2], A0[3], aAdr);
        ldsm4t(A1[0], A1[1], A1[2], A1[3], aAdr + 16 * H_PITCH * 2);
#pragma unroll
        for (int nt = 0; nt < 16; ++nt) {
            uint32_t B0, B1, B2, B3;
            ldsm4t(B0, B1, B2, B3, aBdr + (uint32_t)(nt * 16));
            mma16816(acc + nt * 4, A0, B0, B1);
            mma16816(acc + nt * 4, A1, B2, B3);
        }
        wcur = wnext;
    }

    // ---- full Z reduction (complete in this CTA) ----
    __syncthreads();
    if (t < 128) zs[t] = zacc;
    __syncthreads();
    if (t >= 128) zs[t - 128] += zacc;
    __syncthreads();

    // ---- epilogue: out += numer / Z (out already holds exact h_res) ----
    float* ob = out + ((size_t)b * NMAC + m0) * DOUT;
#pragma unroll
    for (int nt = 0; nt < 16; ++nt) {
        int ma = nt * 8 + tig * 2;
        float iz0 = 1.0f / zs[ma];
        float iz1 = 1.0f / zs[ma + 1];
        int k = kw + g;
        float* p0 = ob + (size_t)ma * DOUT + k;
        float* p1 = ob + (size_t)(ma + 1) * DOUT + k;
        p0[0] += acc[nt * 4 + 0] * iz0;
        p1[0] += acc[nt * 4 + 1] * iz1;
        p0[8] += acc[nt * 4 + 2] * iz0;
        p1[8] += acc[nt * 4 + 3] * iz1;
    }
}

// ---------------- launch ----------------
extern "C" void kernel_launch(void* const* d_in, const int* in_sizes, int n_in,
                              void* d_out, int out_size)
{
    const int*   adj  = (const int*)d_in[0];
    const int*   bidx = (const int*)d_in[1];
    const float* fop  = (const float*)d_in[2];
    const float* fma  = (const float*)d_in[3];
    const float* ow   = (const float*)d_in[4];
    const float* mw   = (const float*)d_in[5];
    const float* oa   = (const float*)d_in[6];
    const float* ma   = (const float*)d_in[7];
    const float* rw   = (const float*)d_in[8];
    float* out = (float*)d_out;

    static bool attr_set = false;
    if (!attr_set) {
        cudaFuncSetAttribute(k3_attn, cudaFuncAttributeMaxDynamicSharedMemorySize, SMEM_K3);
        attr_set = true;
    }

    k_pre<<<PRE_BLOCKS, 256>>>(adj, bidx, fop, ow, oa, fma, rw, mw, ma, out);
    k3_attn<<<NB * 8, 256, SMEM_K3>>>(out);
}

// round 17
// speedup vs baseline: 1.2778x; 1.1395x over previous
#include <cuda_runtime.h>
#include <cuda_bf16.h>
#include <cstdint>

#define NB   32
#define NOPE 2048
#define NMAC 1024
#define DIN  64
#define DOUT 128

#define CHUNK  64
#define NCH    (NOPE / CHUNK)    // 32

#define PACK_BLOCKS (NB * (NOPE / 32))                  // 2048 (int4 pack)
#define K1_BLOCKS   (NB * (NOPE / 32))                  // 2048
#define K2_BLOCKS   (NB * (NMAC / 32))                  // 1024
#define PRE_BLOCKS  (PACK_BLOCKS + K1_BLOCKS + K2_BLOCKS)  // 5120 = 1024*5

// ---------------- scratch (device globals; no allocations) ----------------
__device__ __nv_bfloat16 g_h[(size_t)NB * NOPE * DOUT];   // h_ope bf16 [b][o][k]
__device__ float4 g_sc[NB * NOPE];                        // {ao, exp(ao), exp(.2ao), 0}
__device__ float g_am [NB * NMAC];
__device__ float g_em1[NB * NMAC];
__device__ float g_em2[NB * NMAC];
__device__ uint32_t g_adjp[(size_t)NB * (NOPE / 32) * NMAC];  // packed adjacency bits

// ---------------- K_pre: interleaved pack + h_ope + h_res ----------------
// groups of 5 blocks: 2 pack, 2 h_ope, 1 h_res  -> pipes overlap from t=0
__global__ void __launch_bounds__(256) k_pre(
    const int* __restrict__ adj, const int* __restrict__ bidx,
    const float* __restrict__ fop, const float* __restrict__ owm,
    const float* __restrict__ oal,
    const float* __restrict__ fma, const float* __restrict__ rwm,
    const float* __restrict__ mwm, const float* __restrict__ mal,
    float* __restrict__ out)
{
    __shared__ float wT_s[DIN * 132];   // [d][k], pitch 132, k contiguous
    __shared__ float f_s[32 * 65];
    __shared__ float v_s[DIN];

    const int t   = threadIdx.x;
    const int bid = blockIdx.x;
    const int grp = bid / 5;
    const int r   = bid - grp * 5;

    // ---------- branch A: adjacency bit-pack (int4-vectorized) ----------
    if (r < 2) {
        const int pid = grp * 2 + r;        // [b][ow], 0..2047
        const int b  = pid >> 6;
        const int ow = pid & 63;
        const int aidx = bidx[b];
        const int4* p = (const int4*)(adj + ((size_t)aidx * NOPE + ow * 32) * NMAC) + t;
        uint32_t w0 = 0, w1 = 0, w2 = 0, w3 = 0;
#pragma unroll
        for (int i = 0; i < 32; ++i) {
            int4 v = p[(size_t)i * (NMAC / 4)];
            w0 |= ((uint32_t)v.x & 1u) << i;
            w1 |= ((uint32_t)v.y & 1u) << i;
            w2 |= ((uint32_t)v.z & 1u) << i;
            w3 |= ((uint32_t)v.w & 1u) << i;
        }
        ((uint4*)g_adjp)[((size_t)b * 64 + ow) * (NMAC / 4) + t] =
            make_uint4(w0, w1, w2, w3);
        return;
    }

    const bool isOpe = r < 4;
    const int  blk   = isOpe ? (grp * 2 + (r - 2)) : grp;
    const float* feat = isOpe ? fop : fma;
    const float* wmat = isOpe ? owm : rwm;
    const float* avw  = isOpe ? owm : mwm;
    const float* aal  = isOpe ? oal : mal;
    const int nrowT = isOpe ? NOPE : NMAC;
    const int b  = isOpe ? (blk >> 6) : (blk >> 5);
    const int r0 = isOpe ? ((blk & 63) * 32) : ((blk & 31) * 32);

    for (int i = t; i < DOUT * DIN; i += 256) {
        int k = i >> 6, d = i & 63;
        wT_s[d * 132 + k] = wmat[i];
    }
    const float* fsrc = feat + (size_t)(b * nrowT + r0) * DIN;
    for (int i = t; i < 32 * DIN; i += 256) {
        int rr = i >> 6, d = i & 63;
        f_s[rr * 65 + d] = fsrc[i];
    }
    if (t < DIN) {
        float s = 0.f;
        for (int k = 0; k < DOUT; ++k) s += avw[k * DIN + t] * aal[k];
        v_s[t] = s;
    }
    __syncthreads();

    const int kg = t & 31;      // k = kg*4 .. kg*4+3 (contiguous quad)
    const int rg = t >> 5;
    float acc[4][4];
#pragma unroll
    for (int rr = 0; rr < 4; ++rr)
#pragma unroll
        for (int j = 0; j < 4; ++j) acc[rr][j] = 0.f;

    for (int d = 0; d < DIN; ++d) {
        const float4 wv = *(const float4*)&wT_s[d * 132 + kg * 4];
#pragma unroll
        for (int rr = 0; rr < 4; ++rr) {
            float f = f_s[(rg * 4 + rr) * 65 + d];
            acc[rr][0] += f * wv.x;
            acc[rr][1] += f * wv.y;
            acc[rr][2] += f * wv.z;
            acc[rr][3] += f * wv.w;
        }
    }

    if (isOpe) {
        __nv_bfloat16* hdst = g_h + (size_t)(b * NOPE + r0) * DOUT;
#pragma unroll
        for (int rr = 0; rr < 4; ++rr) {
            __nv_bfloat162 lo = __float22bfloat162_rn(make_float2(acc[rr][0], acc[rr][1]));
            __nv_bfloat162 hi = __float22bfloat162_rn(make_float2(acc[rr][2], acc[rr][3]));
            uint2 v = make_uint2(*(uint32_t*)&lo, *(uint32_t*)&hi);
            *(uint2*)&hdst[(rg * 4 + rr) * DOUT + kg * 4] = v;
        }
        if (t < 32) {
            float ao = 0.f;
            for (int d = 0; d < DIN; ++d) ao += f_s[t * 65 + d] * v_s[d];
            int idx = b * NOPE + r0 + t;
            g_sc[idx] = make_float4(ao, expf(ao), expf(0.2f * ao), 0.f);
        }
    } else {
        float* odst = out + (size_t)(b * NMAC + r0) * DOUT;
#pragma unroll
        for (int rr = 0; rr < 4; ++rr)
            *(float4*)&odst[(rg * 4 + rr) * DOUT + kg * 4] =
                make_float4(acc[rr][0], acc[rr][1], acc[rr][2], acc[rr][3]);
        if (t < 32) {
            float am = 0.f;
            for (int d = 0; d < DIN; ++d) am += f_s[t * 65 + d] * v_s[d];
            int idx = b * NMAC + r0 + t;
            g_am[idx]  = am;
            g_em1[idx] = expf(am);
            g_em2[idx] = expf(0.2f * am);
        }
    }
}

// ---------------- K3: fused masked-softmax aggregation + normalize ----------------
__device__ __forceinline__ void ldsm4t(uint32_t& r0, uint32_t& r1, uint32_t& r2,
                                       uint32_t& r3, uint32_t addr)
{
    asm volatile("ldmatrix.sync.aligned.m8n8.x4.trans.shared.b16 {%0,%1,%2,%3}, [%4];\n"
                 : "=r"(r0), "=r"(r1), "=r"(r2), "=r"(r3) : "r"(addr));
}
__device__ __forceinline__ void mma16816(float* c, const uint32_t* a,
                                         uint32_t b0, uint32_t b1)
{
    asm volatile("mma.sync.aligned.m16n8k16.row.col.f32.bf16.bf16.f32 "
                 "{%0,%1,%2,%3}, {%4,%5,%6,%7}, {%8,%9}, {%0,%1,%2,%3};\n"
                 : "+f"(c[0]), "+f"(c[1]), "+f"(c[2]), "+f"(c[3])
                 : "r"(a[0]), "r"(a[1]), "r"(a[2]), "r"(a[3]), "r"(b0), "r"(b1));
}
__device__ __forceinline__ void cpa16(uint32_t s, const void* g)
{
    asm volatile("cp.async.cg.shared.global [%0], [%1], 16;\n" :: "r"(s), "l"(g));
}
__device__ __forceinline__ void cpa_commit()
{
    asm volatile("cp.async.commit_group;\n" ::);
}

// dynamic smem layout (bytes); 3-stage H pipeline of 64-o chunks
#define H_PITCH   136
#define H_BYTES   (CHUNK * H_PITCH * 2)     // 17408
#define OFF_H     0
#define OFF_W     (3 * H_BYTES)                   // 52224
#define OFF_SC    (OFF_W + H_BYTES)               // 69632
#define OFF_ZS    (OFF_SC + NOPE * 16)            // 102400
#define SMEM_K3   (OFF_ZS + 512)                  // 102912

// grid 256 = 32 b x 8 m-tiles; 256 threads; 2 CTAs/SM -> single wave.
__global__ void __launch_bounds__(256, 2) k3_attn(float* __restrict__ out)
{
    extern __shared__ __align__(16) char sm[];
    __nv_bfloat16* Ws  = (__nv_bfloat16*)(sm + OFF_W);
    float4*        scS = (float4*)(sm + OFF_SC);
    float*         zs  = (float*)(sm + OFF_ZS);

    const int t  = threadIdx.x;
    const int bx = blockIdx.x;
    const int b  = bx >> 3;
    const int mt = bx & 7;
    const int m0 = mt * 128;

    const uint32_t smbase = (uint32_t)__cvta_generic_to_shared(sm);
    const char* hgbase = (const char*)(g_h + (size_t)b * NOPE * DOUT);

    const int m  = t & 127;
    const int oh = t >> 7;

    // packed adjacency: two words per 64-o chunk per thread (layout [b][ow][m])
    const uint32_t* adjw = g_adjp + (size_t)b * (NOPE / 32) * NMAC + m0 + m;

    // stage H chunk ch (64 rows x 128 bf16) into buffer buf
    auto stageH = [&](int ch, int buf) {
        const char* hg = hgbase + (size_t)ch * CHUNK * DOUT * 2;
        uint32_t hD = smbase + OFF_H + (uint32_t)(buf * H_BYTES);
#pragma unroll
        for (int j = 0; j < 4; ++j) {
            int i = t + 256 * j, rr = i >> 4, s = i & 15;
            cpa16(hD + (uint32_t)(rr * H_PITCH * 2 + s * 16),
                  hg + (size_t)rr * DOUT * 2 + s * 16);
        }
    };

    // prologue: H chunks 0,1 in flight; adjacency words for chunk 0
    stageH(0, 0); cpa_commit();
    stageH(1, 1); cpa_commit();
    uint32_t wA = __ldg(adjw);               // o 0..31
    uint32_t wB = __ldg(adjw + NMAC);        // o 32..63

    // fused per-o scalar table (overlaps prologue loads)
    {
        const float4* s0 = g_sc + b * NOPE;
        for (int i = t; i < NOPE; i += 256) scS[i] = s0[i];
    }

    const float amv = g_am [b * NMAC + m0 + m];
    const float em1 = g_em1[b * NMAC + m0 + m];
    const float em2 = g_em2[b * NMAC + m0 + m];
    const float negam = -amv;

    const int warp = t >> 5, lane = t & 31;
    const int wk   = warp & 3;           // k quarter (32 k)
    const int wm   = warp >> 2;          // m half (64 m)
    const int g    = lane >> 2, tig = lane & 3;

    const int a_or = (lane & 7) + ((lane & 16) >> 1);
    const uint32_t aAdr0 = smbase + OFF_H +
        (uint32_t)((a_or * H_PITCH + wk * 32 + (lane & 8)) * 2);
    const uint32_t bAdr0 = smbase + OFF_W +
        (uint32_t)((lane * H_PITCH + wm * 64) * 2);

    float acc[64];
#pragma unroll
    for (int i = 0; i < 64; ++i) acc[i] = 0.f;
    float zacc = 0.f;

    for (int ch = 0; ch < NCH; ++ch) {
        const int buf = ch % 3;
        asm volatile("cp.async.wait_group 1;\n" ::);   // H chunk ch landed
        __syncthreads();                                // visible; old buffers free

        if (ch + 2 < NCH) stageH(ch + 2, (ch + 2) % 3);
        cpa_commit();

        // prefetch next chunk's adjacency words
        uint32_t nA = 0, nB = 0;
        if (ch + 1 < NCH) {
            nA = __ldg(adjw + (size_t)(2 * ch + 2) * NMAC);
            nB = __ldg(adjw + (size_t)(2 * ch + 3) * NMAC);
        }

        // ---- W-gen from packed bits + fused scalar table (64 o x 128 m) ----
        {
            const float4* sc = scS + ch * CHUNK;
#pragma unroll
            for (int j = 0; j < 32; ++j) {
                int ol = oh + 2 * j;
                uint32_t bits = (ol < 32) ? wA : wB;
                int bi = ol & 31;
                float w = 0.f;
                if ((bits >> bi) & 1u) {
                    float4 s = sc[ol];
                    w = (s.x >= negam) ? s.y * em1 : s.z * em2;
                }
                Ws[ol * H_PITCH + m] = __float2bfloat16(w);
                zacc += w;
            }
        }
        __syncthreads();

        // ---- mma phase (64 o per chunk, warp tile 32k x 64m) ----
        const uint32_t aB = aAdr0 + (uint32_t)(buf * H_BYTES);
#pragma unroll
        for (int kh = 0; kh < 2; ++kh) {
            uint32_t A[2][2][4];   // [ks][mi][frag]
#pragma unroll
            for (int ks = 0; ks < 2; ++ks)
#pragma unroll
                for (int mi = 0; mi < 2; ++mi)
                    ldsm4t(A[ks][mi][0], A[ks][mi][1], A[ks][mi][2], A[ks][mi][3],
                           aB + (uint32_t)(((kh * 32 + ks * 16) * H_PITCH + mi * 16) * 2));
#pragma unroll
            for (int nt = 0; nt < 8; ++nt) {
                uint32_t B0, B1, B2, B3;
                ldsm4t(B0, B1, B2, B3,
                       bAdr0 + (uint32_t)(kh * 32 * H_PITCH * 2 + nt * 16));
                mma16816(acc + nt * 4,        A[0][0], B0, B1);
                mma16816(acc + (8 + nt) * 4,  A[0][1], B0, B1);
                mma16816(acc + nt * 4,        A[1][0], B2, B3);
                mma16816(acc + (8 + nt) * 4,  A[1][1], B2, B3);
            }
        }
        wA = nA; wB = nB;
    }

    // ---- full Z reduction (complete in this CTA) ----
    __syncthreads();
    if (t < 128) zs[t] = zacc;
    __syncthreads();
    if (t >= 128) zs[t - 128] += zacc;
    __syncthreads();

    // ---- epilogue: out += numer / Z (out already holds exact h_res) ----
    float* ob = out + ((size_t)b * NMAC + m0) * DOUT;
#pragma unroll
    for (int mi = 0; mi < 2; ++mi)
#pragma unroll
    for (int nt = 0; nt < 8; ++nt) {
        int ma = wm * 64 + nt * 8 + tig * 2;
        int k  = wk * 32 + mi * 16 + g;
        float iz0 = 1.0f / zs[ma];
        float iz1 = 1.0f / zs[ma + 1];
        const int idx = (mi * 8 + nt) * 4;
        float* p0 = ob + (size_t)ma * DOUT + k;
        float* p1 = ob + (size_t)(ma + 1) * DOUT + k;
        p0[0] += acc[idx + 0] * iz0;
        p1[0] += acc[idx + 1] * iz1;
        p0[8] += acc[idx + 2] * iz0;
        p1[8] += acc[idx + 3] * iz1;
    }
}

// ---------------- launch ----------------
extern "C" void kernel_launch(void* const* d_in, const int* in_sizes, int n_in,
                              void* d_out, int out_size)
{
    const int*   adj  = (const int*)d_in[0];
    const int*   bidx = (const int*)d_in[1];
    const float* fop  = (const float*)d_in[2];
    const float* fma  = (const float*)d_in[3];
    const float* ow   = (const float*)d_in[4];
    const float* mw   = (const float*)d_in[5];
    const float* oa   = (const float*)d_in[6];
    const float* ma   = (const float*)d_in[7];
    const float* rw   = (const float*)d_in[8];
    float* out = (float*)d_out;

    static bool attr_set = false;
    if (!attr_set) {
        cudaFuncSetAttribute(k3_attn, cudaFuncAttributeMaxDynamicSharedMemorySize, SMEM_K3);
        attr_set = true;
    }

    k_pre<<<PRE_BLOCKS, 256>>>(adj, bidx, fop, ow, oa, fma, rw, mw, ma, out);
    k3_attn<<<NB * 8, 256, SMEM_K3>>>(out);
}